// round 2
// baseline (speedup 1.0000x reference)
#include <cuda_runtime.h>
#include <math.h>

#define GRID_N   160
#define NVOX     (160*160*160)
#define NSTEPS   256
#define N_LORS   100000
#define EPS      1e-8f

// SIGMA = float32(300.0*0.15/2.355) = 19.108280181884766f
#define SIGMA_F     19.108280181884766f
#define INV_SIGMA   (1.0f / SIGMA_F)
#define C_HALF_F    0.15f
#define Z2_CUTOFF   36.0f   // exp(-18) ~ 1.5e-8 — negligible vs 1e-3 tolerance

// ---------------------------------------------------------------------------
// Pass 1+2 fused: one warp per LOR.
// Lane l handles steps k = j*32 + l, j = 0..7. flat/w kept in registers so the
// expensive exp + index math is computed once and reused for the scatter pass.
//
// Index arithmetic must match the float32 reference BIT-EXACTLY because
// floor() is discontinuous: pts = p0 + (t*d) with two roundings (no FMA!),
// then (pts + 160) * 0.5 (both exact ops re: reference's (pts+160)/2).
// ---------------------------------------------------------------------------
__global__ void __launch_bounds__(256)
lor_kernel(const float* __restrict__ image,
           const float* __restrict__ lors,
           float*       __restrict__ bp)
{
    const int gwarp = (blockIdx.x * blockDim.x + threadIdx.x) >> 5;
    const int lane  = threadIdx.x & 31;
    if (gwarp >= N_LORS) return;

    // Broadcast the 7 LOR floats via lanes 0..6
    const float* l7 = lors + (size_t)gwarp * 7;
    float v = (lane < 7) ? __ldg(l7 + lane) : 0.0f;
    const float p0x = __shfl_sync(0xffffffffu, v, 0);
    const float p0y = __shfl_sync(0xffffffffu, v, 1);
    const float p0z = __shfl_sync(0xffffffffu, v, 2);
    const float p1x = __shfl_sync(0xffffffffu, v, 3);
    const float p1y = __shfl_sync(0xffffffffu, v, 4);
    const float p1z = __shfl_sync(0xffffffffu, v, 5);
    const float tof = __shfl_sync(0xffffffffu, v, 6);

    const float dx = p1x - p0x, dy = p1y - p0y, dz = p1z - p0z;
    const float L  = sqrtf(dx*dx + dy*dy + dz*dz);
    const float dl = L * (1.0f / NSTEPS);
    const float s_tof = tof * C_HALF_F;

    int   flat[8];
    float w[8];
    float p = 0.0f;

    #pragma unroll
    for (int j = 0; j < 8; ++j) {
        const int   k  = j * 32 + lane;
        const float t  = ((float)k + 0.5f) * (1.0f / NSTEPS);
        const float s  = (t - 0.5f) * L;
        const float z  = (s - s_tof) * INV_SIGMA;
        const float z2 = z * z;

        // Warp-uniform skip: whole 32-step span outside the TOF window
        const unsigned act = __ballot_sync(0xffffffffu, z2 < Z2_CUTOFF);
        if (act == 0u) { flat[j] = 0; w[j] = 0.0f; continue; }

        // pts = p0 + t*d  — two roundings, exactly like the float32 reference
        const float px = __fadd_rn(p0x, __fmul_rn(t, dx));
        const float py = __fadd_rn(p0y, __fmul_rn(t, dy));
        const float pz = __fadd_rn(p0z, __fmul_rn(t, dz));
        // idx = floor((pts + 160) / 2) — both ops exact w.r.t. reference
        const int ix = (int)floorf(__fmul_rn(__fadd_rn(px, 160.0f), 0.5f));
        const int iy = (int)floorf(__fmul_rn(__fadd_rn(py, 160.0f), 0.5f));
        const int iz = (int)floorf(__fmul_rn(__fadd_rn(pz, 160.0f), 0.5f));
        const bool inb = ((unsigned)ix < (unsigned)GRID_N) &
                         ((unsigned)iy < (unsigned)GRID_N) &
                         ((unsigned)iz < (unsigned)GRID_N);

        float ww = 0.0f;
        int   f  = 0;
        if (inb & (z2 < Z2_CUTOFF)) {
            ww = __expf(-0.5f * z2) * dl;
            f  = (ix * GRID_N + iy) * GRID_N + iz;
            p += __ldg(image + f) * ww;
        }
        flat[j] = f;
        w[j]    = ww;
    }

    // Warp-reduce p (full-warp butterfly)
    #pragma unroll
    for (int off = 16; off > 0; off >>= 1)
        p += __shfl_xor_sync(0xffffffffu, p, off);

    // Scatter: bp[flat] += p * w   (skip zero-weight lanes)
    #pragma unroll
    for (int j = 0; j < 8; ++j) {
        if (w[j] != 0.0f)
            atomicAdd(bp + flat[j], p * w[j]);
    }
}

// ---------------------------------------------------------------------------
// Epilogue: out = image / (effmap + eps) * bp   (out aliases bp, in-place)
// ---------------------------------------------------------------------------
__global__ void __launch_bounds__(256)
finish_kernel(const float* __restrict__ image,
              const float* __restrict__ effmap,
              float*       __restrict__ out)
{
    const int i = blockIdx.x * blockDim.x + threadIdx.x;
    if (i * 4 >= NVOX) return;
    float4 im = __ldg((const float4*)image  + i);
    float4 ef = __ldg((const float4*)effmap + i);
    float4 b  = ((const float4*)out)[i];
    float4 r;
    r.x = __fdividef(im.x, ef.x + EPS) * b.x;
    r.y = __fdividef(im.y, ef.y + EPS) * b.y;
    r.z = __fdividef(im.z, ef.z + EPS) * b.z;
    r.w = __fdividef(im.w, ef.w + EPS) * b.w;
    ((float4*)out)[i] = r;
}

extern "C" void kernel_launch(void* const* d_in, const int* in_sizes, int n_in,
                              void* d_out, int out_size)
{
    const float* image  = (const float*)d_in[0];
    const float* effmap = (const float*)d_in[1];
    const float* lors   = (const float*)d_in[2];
    float* out = (float*)d_out;

    // bp accumulator lives in d_out; zero it first (capturable memset node)
    cudaMemsetAsync(out, 0, (size_t)NVOX * sizeof(float), 0);

    // 100000 warps, 8 warps/block
    const int threads = 256;
    const int blocks  = (N_LORS * 32 + threads - 1) / threads;
    lor_kernel<<<blocks, threads>>>(image, lors, out);

    const int n4 = NVOX / 4;
    finish_kernel<<<(n4 + 255) / 256, 256>>>(image, effmap, out);
}

// round 3
// speedup vs baseline: 1.1582x; 1.1582x over previous
#include <cuda_runtime.h>
#include <math.h>

#define GRID_N   160
#define NVOX     (160*160*160)
#define NSTEPS   256
#define N_LORS   100000
#define EPS      1e-8f

// SIGMA = float32(300.0*0.15/2.355) = 19.108280181884766f
#define SIGMA_F     19.108280181884766f
#define INV_SIGMA   (1.0f / SIGMA_F)
#define C_HALF_F    0.15f
// Cutoff z^2 < 18 -> truncated weights < exp(-9) = 1.2e-4 of peak.
// Integrated tail error ~1e-5 in a global-norm metric (threshold 1e-3).
#define Z2_CUTOFF   18.0f
#define W_CUT       4.2426406871f          // sqrt(18)
#define S_HALFWIN   (W_CUT * SIGMA_F)      // 81.07 mm

// ---------------------------------------------------------------------------
// One warp per LOR. Lane l handles steps k = j*32 + l. flat/w kept in
// registers (fully unrolled, constant indices) so exp + index math is
// computed once and reused for the scatter pass.
//
// Active j-span [jlo, jhi] computed analytically from the TOF window so dead
// spans cost one uniform compare.
//
// Index path matches the float32 reference BIT-EXACTLY (floor is
// discontinuous): pts = p0 + (t*d) with two roundings (no FMA), then
// (pts + 160) * 0.5 (exact ops).
// ---------------------------------------------------------------------------
__global__ void __launch_bounds__(256)
lor_kernel(const float* __restrict__ image,
           const float* __restrict__ lors,
           float*       __restrict__ bp)
{
    const int gwarp = (blockIdx.x * blockDim.x + threadIdx.x) >> 5;
    const int lane  = threadIdx.x & 31;
    if (gwarp >= N_LORS) return;

    // Broadcast the 7 LOR floats via lanes 0..6
    const float* l7 = lors + (size_t)gwarp * 7;
    float v = (lane < 7) ? __ldg(l7 + lane) : 0.0f;
    const float p0x = __shfl_sync(0xffffffffu, v, 0);
    const float p0y = __shfl_sync(0xffffffffu, v, 1);
    const float p0z = __shfl_sync(0xffffffffu, v, 2);
    const float p1x = __shfl_sync(0xffffffffu, v, 3);
    const float p1y = __shfl_sync(0xffffffffu, v, 4);
    const float p1z = __shfl_sync(0xffffffffu, v, 5);
    const float tof = __shfl_sync(0xffffffffu, v, 6);

    const float dx = p1x - p0x, dy = p1y - p0y, dz = p1z - p0z;
    const float L  = sqrtf(dx*dx + dy*dy + dz*dz);
    const float dl = L * (1.0f / NSTEPS);
    const float s_tof = tof * C_HALF_F;

    // Analytic active step range: s(k) = ((k+0.5)/256 - 0.5)*L in
    // [s_tof - S_HALFWIN, s_tof + S_HALFWIN]  ->  k = s/L*256 + 127.5
    const float invL  = __fdividef(1.0f, L);          // inf if L==0 (w=0 anyway)
    const float klo_f = fmaf((s_tof - S_HALFWIN) * invL, 256.0f, 127.5f);
    const float khi_f = fmaf((s_tof + S_HALFWIN) * invL, 256.0f, 127.5f);
    const int jlo = ((int)fmaxf(0.0f, fminf(255.0f, klo_f))) >> 5;
    const int jhi = ((int)fmaxf(0.0f, fminf(255.0f, khi_f))) >> 5;

    int   flat[8];
    float w[8];
    float p = 0.0f;

    #pragma unroll
    for (int j = 0; j < 8; ++j) {
        w[j] = 0.0f;
        flat[j] = 0;
        if (j < jlo || j > jhi) continue;   // warp-uniform skip

        const int   k  = j * 32 + lane;
        const float t  = ((float)k + 0.5f) * (1.0f / NSTEPS);
        const float s  = (t - 0.5f) * L;
        const float z  = (s - s_tof) * INV_SIGMA;
        const float z2 = z * z;

        // pts = p0 + t*d  — two roundings, exactly like the float32 reference
        const float px = __fadd_rn(p0x, __fmul_rn(t, dx));
        const float py = __fadd_rn(p0y, __fmul_rn(t, dy));
        const float pz = __fadd_rn(p0z, __fmul_rn(t, dz));
        // idx = floor((pts + 160) / 2) — both ops exact w.r.t. reference
        const int ix = (int)floorf(__fmul_rn(__fadd_rn(px, 160.0f), 0.5f));
        const int iy = (int)floorf(__fmul_rn(__fadd_rn(py, 160.0f), 0.5f));
        const int iz = (int)floorf(__fmul_rn(__fadd_rn(pz, 160.0f), 0.5f));
        const bool inb = ((unsigned)ix < (unsigned)GRID_N) &
                         ((unsigned)iy < (unsigned)GRID_N) &
                         ((unsigned)iz < (unsigned)GRID_N);

        if (inb & (z2 < Z2_CUTOFF)) {
            const float ww = __expf(-0.5f * z2) * dl;
            const int   f  = (ix * GRID_N + iy) * GRID_N + iz;
            p += __ldg(image + f) * ww;
            w[j]    = ww;
            flat[j] = f;
        }
    }

    // Warp-reduce p (full-warp butterfly)
    #pragma unroll
    for (int off = 16; off > 0; off >>= 1)
        p += __shfl_xor_sync(0xffffffffu, p, off);

    // Scatter: bp[flat] += p * w   (w stays 0 outside [jlo,jhi])
    #pragma unroll
    for (int j = 0; j < 8; ++j) {
        if (w[j] != 0.0f)
            atomicAdd(bp + flat[j], p * w[j]);
    }
}

// ---------------------------------------------------------------------------
// Epilogue: out = image / (effmap + eps) * bp   (out aliases bp, in-place)
// ---------------------------------------------------------------------------
__global__ void __launch_bounds__(256)
finish_kernel(const float* __restrict__ image,
              const float* __restrict__ effmap,
              float*       __restrict__ out)
{
    const int i = blockIdx.x * blockDim.x + threadIdx.x;
    if (i * 4 >= NVOX) return;
    float4 im = __ldg((const float4*)image  + i);
    float4 ef = __ldg((const float4*)effmap + i);
    float4 b  = ((const float4*)out)[i];
    float4 r;
    r.x = __fdividef(im.x, ef.x + EPS) * b.x;
    r.y = __fdividef(im.y, ef.y + EPS) * b.y;
    r.z = __fdividef(im.z, ef.z + EPS) * b.z;
    r.w = __fdividef(im.w, ef.w + EPS) * b.w;
    ((float4*)out)[i] = r;
}

extern "C" void kernel_launch(void* const* d_in, const int* in_sizes, int n_in,
                              void* d_out, int out_size)
{
    const float* image  = (const float*)d_in[0];
    const float* effmap = (const float*)d_in[1];
    const float* lors   = (const float*)d_in[2];
    float* out = (float*)d_out;

    // bp accumulator lives in d_out; zero it first (capturable memset node)
    cudaMemsetAsync(out, 0, (size_t)NVOX * sizeof(float), 0);

    // 100000 warps, 8 warps/block
    const int threads = 256;
    const int blocks  = (N_LORS * 32 + threads - 1) / threads;
    lor_kernel<<<blocks, threads>>>(image, lors, out);

    const int n4 = NVOX / 4;
    finish_kernel<<<(n4 + 255) / 256, 256>>>(image, effmap, out);
}

// round 4
// speedup vs baseline: 1.1701x; 1.0103x over previous
#include <cuda_runtime.h>
#include <math.h>

#define GRID_N   160
#define NVOX     (160*160*160)
#define NSTEPS   256
#define N_LORS   100000
#define EPS      1e-8f

// SIGMA = float32(300.0*0.15/2.355) = 19.108280181884766f
#define SIGMA_F     19.108280181884766f
#define INV_SIGMA   (1.0f / SIGMA_F)
#define C_HALF_F    0.15f
#define Z2_CUTOFF   18.0f
#define W_CUT       4.2426406871f          // sqrt(18)
#define S_HALFWIN   (W_CUT * SIGMA_F)      // 81.07 mm

// ---------------------------------------------------------------------------
// One warp per LOR. Lane handles TWO consecutive steps per span:
// k0 = j*64 + 2*lane, k1 = k0+1, j = 0..3. Consecutive steps often land in
// the SAME voxel (dl ~1.2-2mm vs 2mm voxels) -> merged single atomic.
// flat/w kept in registers so exp + index math is computed once and reused
// for the scatter pass.
//
// Index path matches the float32 reference BIT-EXACTLY (floor is
// discontinuous): pts = p0 + (t*d) with two roundings (no FMA), then
// (pts + 160) * 0.5 (exact ops).
// ---------------------------------------------------------------------------
__device__ __forceinline__ void sample_step(
    int k, float L, float s_tof,
    float p0x, float p0y, float p0z,
    float dx, float dy, float dz, float dl,
    const float* __restrict__ image,
    float& p, int& f, float& ww)
{
    const float t  = ((float)k + 0.5f) * (1.0f / NSTEPS);
    const float s  = (t - 0.5f) * L;
    const float z  = (s - s_tof) * INV_SIGMA;
    const float z2 = z * z;

    // pts = p0 + t*d — two roundings, exactly like the float32 reference
    const float px = __fadd_rn(p0x, __fmul_rn(t, dx));
    const float py = __fadd_rn(p0y, __fmul_rn(t, dy));
    const float pz = __fadd_rn(p0z, __fmul_rn(t, dz));
    const int ix = (int)floorf(__fmul_rn(__fadd_rn(px, 160.0f), 0.5f));
    const int iy = (int)floorf(__fmul_rn(__fadd_rn(py, 160.0f), 0.5f));
    const int iz = (int)floorf(__fmul_rn(__fadd_rn(pz, 160.0f), 0.5f));
    const bool inb = ((unsigned)ix < (unsigned)GRID_N) &
                     ((unsigned)iy < (unsigned)GRID_N) &
                     ((unsigned)iz < (unsigned)GRID_N);

    f  = 0;
    ww = 0.0f;
    if (inb & (z2 < Z2_CUTOFF)) {
        ww = __expf(-0.5f * z2) * dl;
        f  = (ix * GRID_N + iy) * GRID_N + iz;
        p += __ldg(image + f) * ww;
    }
}

__global__ void __launch_bounds__(256)
lor_kernel(const float* __restrict__ image,
           const float* __restrict__ lors,
           float*       __restrict__ bp)
{
    const int gwarp = (blockIdx.x * blockDim.x + threadIdx.x) >> 5;
    const int lane  = threadIdx.x & 31;
    if (gwarp >= N_LORS) return;

    // Broadcast the 7 LOR floats via lanes 0..6
    const float* l7 = lors + (size_t)gwarp * 7;
    float v = (lane < 7) ? __ldg(l7 + lane) : 0.0f;
    const float p0x = __shfl_sync(0xffffffffu, v, 0);
    const float p0y = __shfl_sync(0xffffffffu, v, 1);
    const float p0z = __shfl_sync(0xffffffffu, v, 2);
    const float p1x = __shfl_sync(0xffffffffu, v, 3);
    const float p1y = __shfl_sync(0xffffffffu, v, 4);
    const float p1z = __shfl_sync(0xffffffffu, v, 5);
    const float tof = __shfl_sync(0xffffffffu, v, 6);

    const float dx = p1x - p0x, dy = p1y - p0y, dz = p1z - p0z;
    const float L  = sqrtf(dx*dx + dy*dy + dz*dz);
    const float dl = L * (1.0f / NSTEPS);
    const float s_tof = tof * C_HALF_F;

    // Analytic active step range over 64-step spans
    const float invL  = __fdividef(1.0f, L);
    const float klo_f = fmaf((s_tof - S_HALFWIN) * invL, 256.0f, 127.5f);
    const float khi_f = fmaf((s_tof + S_HALFWIN) * invL, 256.0f, 127.5f);
    const int jlo = ((int)fmaxf(0.0f, fminf(255.0f, klo_f))) >> 6;
    const int jhi = ((int)fmaxf(0.0f, fminf(255.0f, khi_f))) >> 6;

    int   f0[4], f1[4];
    float w0[4], w1[4];
    float p = 0.0f;

    #pragma unroll
    for (int j = 0; j < 4; ++j) {
        f0[j] = f1[j] = 0;
        w0[j] = w1[j] = 0.0f;
        if (j < jlo || j > jhi) continue;   // warp-uniform skip

        const int k0 = j * 64 + lane * 2;
        sample_step(k0,     L, s_tof, p0x, p0y, p0z, dx, dy, dz, dl, image, p, f0[j], w0[j]);
        sample_step(k0 + 1, L, s_tof, p0x, p0y, p0z, dx, dy, dz, dl, image, p, f1[j], w1[j]);
    }

    // Warp-reduce p (full-warp butterfly)
    #pragma unroll
    for (int off = 16; off > 0; off >>= 1)
        p += __shfl_xor_sync(0xffffffffu, p, off);

    // Scatter with same-voxel pair merging. Merging with a zero weight is
    // harmless (flat defaults to 0), so flat equality alone decides.
    #pragma unroll
    for (int j = 0; j < 4; ++j) {
        if (f0[j] == f1[j]) {
            const float ws = w0[j] + w1[j];
            if (ws != 0.0f) atomicAdd(bp + f0[j], p * ws);
        } else {
            if (w0[j] != 0.0f) atomicAdd(bp + f0[j], p * w0[j]);
            if (w1[j] != 0.0f) atomicAdd(bp + f1[j], p * w1[j]);
        }
    }
}

// ---------------------------------------------------------------------------
// Epilogue: out = image / (effmap + eps) * bp (in-place), 2 independent
// float4 streams per thread for memory-level parallelism.
// ---------------------------------------------------------------------------
#define N4      (NVOX / 4)        // 1024000
#define N4_HALF (N4 / 2)          // 512000

__global__ void __launch_bounds__(256)
finish_kernel(const float* __restrict__ image,
              const float* __restrict__ effmap,
              float*       __restrict__ out)
{
    const int i = blockIdx.x * blockDim.x + threadIdx.x;
    if (i >= N4_HALF) return;
    const int i2 = i + N4_HALF;

    float4 imA = __ldg((const float4*)image  + i);
    float4 efA = __ldg((const float4*)effmap + i);
    float4 bA  = ((const float4*)out)[i];
    float4 imB = __ldg((const float4*)image  + i2);
    float4 efB = __ldg((const float4*)effmap + i2);
    float4 bB  = ((const float4*)out)[i2];

    float4 rA, rB;
    rA.x = __fdividef(imA.x, efA.x + EPS) * bA.x;
    rA.y = __fdividef(imA.y, efA.y + EPS) * bA.y;
    rA.z = __fdividef(imA.z, efA.z + EPS) * bA.z;
    rA.w = __fdividef(imA.w, efA.w + EPS) * bA.w;
    rB.x = __fdividef(imB.x, efB.x + EPS) * bB.x;
    rB.y = __fdividef(imB.y, efB.y + EPS) * bB.y;
    rB.z = __fdividef(imB.z, efB.z + EPS) * bB.z;
    rB.w = __fdividef(imB.w, efB.w + EPS) * bB.w;

    ((float4*)out)[i]  = rA;
    ((float4*)out)[i2] = rB;
}

// No-op kernel: shifts ncu's -s 5 -c 1 capture window onto lor_kernel
// (4 launches/replay -> profiled launch index 5 = replay 2's lor_kernel).
__global__ void probe_kernel() {}

extern "C" void kernel_launch(void* const* d_in, const int* in_sizes, int n_in,
                              void* d_out, int out_size)
{
    const float* image  = (const float*)d_in[0];
    const float* effmap = (const float*)d_in[1];
    const float* lors   = (const float*)d_in[2];
    float* out = (float*)d_out;

    cudaMemsetAsync(out, 0, (size_t)NVOX * sizeof(float), 0);

    const int threads = 256;
    const int blocks  = (N_LORS * 32 + threads - 1) / threads;
    lor_kernel<<<blocks, threads>>>(image, lors, out);

    finish_kernel<<<(N4_HALF + 255) / 256, 256>>>(image, effmap, out);

    probe_kernel<<<1, 1>>>();
}